// round 8
// baseline (speedup 1.0000x reference)
#include <cuda_runtime.h>

typedef unsigned long long u64;

// ---- packed f32x2 helpers (Blackwell; ptxas won't auto-fuse) ----
static __device__ __forceinline__ u64 pack2(float v) {
    u64 r; asm("mov.b64 %0, {%1, %1};" : "=l"(r) : "f"(v)); return r;
}
static __device__ __forceinline__ u64 mul2(u64 a, u64 b) {
    u64 r; asm("mul.rn.f32x2 %0, %1, %2;" : "=l"(r) : "l"(a), "l"(b)); return r;
}
static __device__ __forceinline__ u64 fma2(u64 a, u64 b, u64 c) {
    u64 r; asm("fma.rn.f32x2 %0, %1, %2, %3;" : "=l"(r) : "l"(a), "l"(b), "l"(c)); return r;
}
// non-coherent 8B load; dense across the warp (32 lanes x 8B contiguous -> 2 lines/request)
static __device__ __forceinline__ u64 ldg64(const u64* p) {
    u64 r; asm("ld.global.nc.b64 %0, [%1];" : "=l"(r) : "l"(p)); return r;
}
// streaming stores: keep the 91MB output from evicting the ~78MB feature set in L2
static __device__ __forceinline__ void st64cs(float* p, u64 a) {
    asm volatile("st.global.cs.u64 [%0], %1;" :: "l"(p), "l"(a));
}
static __device__ __forceinline__ void st32cs(float* p, float a) {
    asm volatile("st.global.cs.f32 [%0], %1;" :: "l"(p), "f"(a));
}

// Multi-res trilinear sampling. Levels 1 (64^3x32), 2 (32^3x64), 3 (16^3x128).
// Out per point: [32 | 64 | 128 | mesh 3] = 227 floats.
// 128 threads/point, 2 channels (one float2) per thread:
//   slot 0..15   -> lev1   slot 16..47 -> lev2
//   slot 48..111 -> lev3   slot 112    -> mesh passthrough (3 floats)
// Global out channel = 2*slot for slots 0..111 (concat offsets align:
// lev2 starts at ch 32 = 2*16, lev3 at ch 96 = 2*48).
__global__ void __launch_bounds__(256) trilerp_kernel(
    const float* __restrict__ f1, const float* __restrict__ f2, const float* __restrict__ f3,
    const float* __restrict__ coords, const float* __restrict__ meshf,
    float* __restrict__ out, int Npts)
{
    int t = blockIdx.x * 256 + threadIdx.x;
    int pInB = t >> 7;
    if (pInB >= Npts) return;
    int slot = t & 127;
    int b = blockIdx.y;
    int point = b * Npts + pInB;
    size_t obase = (size_t)point * 227;

    if (slot >= 112) {
        if (slot == 112) {
            st32cs(out + obase + 224, __ldg(meshf + point * 3 + 0));
            st32cs(out + obase + 225, __ldg(meshf + point * 3 + 1));
            st32cs(out + obase + 226, __ldg(meshf + point * 3 + 2));
        }
        return;
    }

    float cx = __ldg(coords + point * 3 + 0);
    float cy = __ldg(coords + point * 3 + 1);
    float cz = __ldg(coords + point * 3 + 2);

    int lev = (slot < 16) ? 1 : ((slot < 48) ? 2 : 3);
    const float* __restrict__ feat = (lev == 1) ? f1 : ((lev == 2) ? f2 : f3);
    int cstart = (lev == 1) ? 0 : ((lev == 2) ? 16 : 48);
    int R  = 128 >> lev;          // 64 / 32 / 16
    int s2 = 8 << lev;            // C/2 = 16 / 32 / 64 (float2 units)  [R7 bug: was 16<<lev]
    int c2 = slot - cstart;       // channel base in float2 units

    float scale = (float)R;       // 0.5^lev * 128 == R
    float hi = scale - 1.01f;
    float ix = fminf(fmaxf(cx * scale, 0.01f), hi);
    float iy = fminf(fmaxf(cy * scale, 0.01f), hi);
    float iz = fminf(fmaxf(cz * scale, 0.01f), hi);

    float fx1 = floorf(ix), fx2 = ceilf(ix);
    float fy1 = floorf(iy), fy2 = ceilf(iy);
    float fz1 = floorf(iz), fz2 = ceilf(iz);

    u64 WX = pack2(ix - fx1), WX2 = pack2(fx2 - ix);
    u64 WY = pack2(iy - fy1), WY2 = pack2(fy2 - iy);
    u64 WZ = pack2(iz - fz1), WZ2 = pack2(fz2 - iz);

    int x1 = (int)fx1, y1 = (int)fy1, z1 = (int)fz1;
    // corner step offsets (0 or one full stride) in float2 units
    int dxs = ((int)fx2 - x1) * R * R * s2;
    int dys = ((int)fy2 - y1) * R * s2;
    int dzs = ((int)fz2 - z1) * s2;
    const u64* p = (const u64*)feat + (((b * R + x1) * R + y1) * R + z1) * s2 + c2;

    // 8 independent dense LDG.64s (front-batched; bytes/wavefront at the floor)
    u64 v111 = ldg64(p);
    u64 v211 = ldg64(p + dxs);
    u64 v121 = ldg64(p + dys);
    u64 v221 = ldg64(p + dxs + dys);
    u64 v112 = ldg64(p + dzs);
    u64 v212 = ldg64(p + dxs + dzs);
    u64 v122 = ldg64(p + dys + dzs);
    u64 v222 = ldg64(p + dxs + dys + dzs);

    // z = z1 plane
    u64 la = fma2(v211, WX, mul2(v111, WX2));
    u64 lb = fma2(v221, WX, mul2(v121, WX2));
    u64 l1 = fma2(lb, WY, mul2(la, WY2));
    // z = z2 plane
    u64 lc = fma2(v212, WX, mul2(v112, WX2));
    u64 ld = fma2(v222, WX, mul2(v122, WX2));
    u64 l2 = fma2(ld, WY, mul2(lc, WY2));

    u64 r = fma2(l2, WZ, mul2(l1, WZ2));

    // out alignment class is warp-uniform (2*slot even; obase parity fixed per point)
    float* q = out + obase + 2 * slot;
    if ((obase & 1) == 0) {
        st64cs(q, r);                               // STG.64
    } else {
        float r0, r1;
        asm("mov.b64 {%0,%1}, %2;" : "=f"(r0), "=f"(r1) : "l"(r));
        st32cs(q + 0, r0);
        st32cs(q + 1, r1);
    }
}

extern "C" void kernel_launch(void* const* d_in, const int* in_sizes, int n_in,
                              void* d_out, int out_size)
{
    // metadata order: features0..features4, mesh_coords, mesh_features
    const float* f1     = (const float*)d_in[1];
    const float* f2     = (const float*)d_in[2];
    const float* f3     = (const float*)d_in[3];
    const float* coords = (const float*)d_in[5];
    const float* meshf  = (const float*)d_in[6];
    float* out = (float*)d_out;

    int B    = in_sizes[1] / (64 * 64 * 64 * 32);
    int BN   = in_sizes[5] / 3;
    int Npts = BN / B;

    long long tpb = (long long)Npts * 128;
    dim3 grid((unsigned)((tpb + 255) / 256), (unsigned)B);
    trilerp_kernel<<<grid, 256>>>(f1, f2, f3, coords, meshf, out, Npts);
}